// round 1
// baseline (speedup 1.0000x reference)
#include <cuda_runtime.h>

// Signature-kernel MMD on GB300.
// x,y: (32, 64, 4) fp32. SIGMA=1, DYADIC_ORDER=1 -> coarse inc 63x63, refined M=126.
// One warp per path-pair: gram -> in-place increments (pre-folded 0.25*inc-1) ->
// antidiagonal Goursat PDE in registers (4 cells/lane). Symmetric xx/yy pairs
// computed once with weight 2 (fp-exact symmetry). Deterministic 2-kernel reduce.

#define BSZ 32
#define LEN 64
#define DIM 4
#define LC 63                    // coarse increment dim
#define GS 64                    // smem row stride (floats)
#define WBUF (64*GS + 2*LEN*DIM) // 4608 floats per warp: gram/inc buffer + A,B points
#define NTRI ((BSZ*(BSZ+1))/2)   // 528
#define NTASKS (2*NTRI + BSZ*BSZ) // 2080
#define WPC 2                    // warps (tasks) per CTA

__device__ float g_partial[NTASKS];

__global__ void __launch_bounds__(32*WPC)
sig_pde_kernel(const float* __restrict__ x, const float* __restrict__ y)
{
    extern __shared__ float smem[];
    const int lane = threadIdx.x & 31;
    const int wid  = threadIdx.x >> 5;
    const int task = blockIdx.x * WPC + wid;
    if (task >= NTASKS) return;

    float* buf = smem + wid * WBUF;   // 64x64 gram, later rows 0..62 hold 0.25*inc-1
    float* sA  = buf + 64*GS;
    float* sB  = sA + LEN*DIM;

    // ---- decode task -> pair pointers + weight ----
    const float *pa, *pb;
    float weight;
    {
        int t = task;
        if (t < 2*NTRI) {
            const float* base = (t < NTRI) ? x : y;
            if (t >= NTRI) t -= NTRI;
            int a = 0;
            while (t >= (BSZ - a)) { t -= (BSZ - a); ++a; }
            int b = a + t;
            pa = base + a*(LEN*DIM);
            pb = base + b*(LEN*DIM);
            weight = (a == b ? 1.0f : 2.0f) * (1.0f/(float)(BSZ*BSZ));
        } else {
            t -= 2*NTRI;
            pa = x + (t >> 5)*(LEN*DIM);
            pb = y + (t & 31)*(LEN*DIM);
            weight = -2.0f/(float)(BSZ*BSZ);
        }
    }

    // ---- stage the two paths into smem ----
    for (int k2 = lane; k2 < LEN*DIM; k2 += 32) { sA[k2] = pa[k2]; sB[k2] = pb[k2]; }
    __syncwarp();

    // ---- RBF gram: G[i][j] = exp(-0.5*|A_i - B_j|^2) ----
    for (int c = lane; c < LEN*LEN; c += 32) {
        int i = c >> 6, j = c & 63;
        float4 a4 = *reinterpret_cast<const float4*>(sA + 4*i);
        float4 b4 = *reinterpret_cast<const float4*>(sB + 4*j);
        float dx = a4.x-b4.x, dy = a4.y-b4.y, dz = a4.z-b4.z, dw = a4.w-b4.w;
        float d2 = dx*dx + dy*dy + dz*dz + dw*dw;
        buf[i*GS + j] = expf(-0.5f * d2);
    }
    __syncwarp();

    // ---- second differences, in place, pre-folded: store 0.25*inc - 1 ----
    // row u reads gram rows u,u+1 then overwrites row u (row u+1 untouched).
    for (int u = 0; u < LC; ++u) {
        int v0 = lane, v1 = lane + 32;
        float g00 = buf[u*GS + v0],     g01 = buf[u*GS + v0 + 1];
        float g10 = buf[(u+1)*GS + v0], g11 = buf[(u+1)*GS + v0 + 1];
        float r0 = fmaf(0.25f, (g11 - g10) - (g01 - g00), -1.0f);
        float r1 = 0.0f;
        if (v1 < LC) {
            float h00 = buf[u*GS + v1],     h01 = buf[u*GS + v1 + 1];
            float h10 = buf[(u+1)*GS + v1], h11 = buf[(u+1)*GS + v1 + 1];
            r1 = fmaf(0.25f, (h11 - h10) - (h01 - h00), -1.0f);
        }
        __syncwarp();
        buf[u*GS + v0] = r0;
        if (v1 < LC) buf[u*GS + v1] = r1;
        __syncwarp();
    }

    // ---- Goursat PDE, antidiagonal wavefront ----
    // Grid (M+1)x(M+1)=127x127, diagonals d=0..252. Lane holds i = 4*lane + k.
    // K[i,j] = K[i-1,j] + K[i,j-1] + K[i-1,j-1]*(inc[i-1,j-1]-1); K[0,*]=K[*,0]=1.
    const int i0 = lane << 2;
    float P2[4], P1[4];               // diag d-2, d-1
    const float* rb[4];               // per-cell coarse-inc row base (fixed: i fixed)
    bool validi[4];
    #pragma unroll
    for (int k = 0; k < 4; ++k) {
        int i = i0 + k;
        P2[k] = (i == 0) ? 1.0f : 0.0f;   // diag 0
        P1[k] = (i <= 1) ? 1.0f : 0.0f;   // diag 1
        int im = (i < 1) ? 1 : i;
        rb[k] = buf + ((im - 1) >> 1) * GS;
        validi[k] = (i >= 1) && (i <= 126);
    }
    const bool isL0 = (lane == 0);

    auto step = [&](int d, float (&Pw)[4], const float (&Pr)[4]) {
        // Pr = diag d-1, Pw = diag d-2 on entry; writes diag d into Pw.
        float p1top = __shfl_up_sync(0xffffffffu, Pr[3], 1);
        float p2top = __shfl_up_sync(0xffffffffu, Pw[3], 1);
        float o0 = Pw[0], o1 = Pw[1], o2 = Pw[2];
        int e = d - i0 - 1;               // ek = j-1 for cell k
        #pragma unroll
        for (int k = 0; k < 4; ++k) {
            int ek = e - k;
            float lp1 = (k == 0) ? p1top : Pr[k-1];
            float lp2;
            if      (k == 0) lp2 = p2top;
            else if (k == 1) lp2 = o0;
            else if (k == 2) lp2 = o1;
            else             lp2 = o2;
            // masked index keeps the (discarded) out-of-range loads in-buffer
            float incm1 = rb[k][(ek >> 1) & 63];
            float val = fmaf(lp2, incm1, lp1) + Pr[k];
            bool interior = validi[k] && ((unsigned)ek < 126u);
            float cc = interior ? val : ((ek == -1) ? 1.0f : 0.0f); // i==d boundary
            if (k == 0) { if (isL0) cc = 1.0f; }                    // i==0 boundary
            Pw[k] = cc;
        }
    };

    for (int d = 2; d < 252; d += 2) {
        step(d,   P2, P1);
        step(d+1, P1, P2);
    }
    step(252, P2, P1);   // final diagonal -> P2

    // K[126,126]: i=126 = 4*31+2 -> lane 31, slot 2
    float res = __shfl_sync(0xffffffffu, P2[2], 31);
    if (lane == 0) g_partial[task] = res * weight;
}

__global__ void sig_reduce_kernel(float* __restrict__ out)
{
    __shared__ double ssum[256];
    double s = 0.0;
    for (int i = threadIdx.x; i < NTASKS; i += 256) s += (double)g_partial[i];
    ssum[threadIdx.x] = s;
    __syncthreads();
    for (int w = 128; w > 0; w >>= 1) {
        if (threadIdx.x < w) ssum[threadIdx.x] += ssum[threadIdx.x + w];
        __syncthreads();
    }
    if (threadIdx.x == 0) out[0] = (float)ssum[0];
}

extern "C" void kernel_launch(void* const* d_in, const int* in_sizes, int n_in,
                              void* d_out, int out_size)
{
    const float* x = (const float*)d_in[0];
    const float* y = (const float*)d_in[1];
    (void)in_sizes; (void)n_in; (void)out_size;

    const int nblocks = (NTASKS + WPC - 1) / WPC;           // 1040
    const size_t shmem = (size_t)WPC * WBUF * sizeof(float); // 36864 B
    sig_pde_kernel<<<nblocks, 32*WPC, shmem>>>(x, y);
    sig_reduce_kernel<<<1, 256>>>((float*)d_out);
}